// round 1
// baseline (speedup 1.0000x reference)
#include <cuda_runtime.h>
#include <float.h>
#include <stdint.h>

#define BB 32
#define NN 2048
#define TPB 256
#define PPT 2                 // source points per thread
#define CHUNK (TPB*PPT)       // 512 source points per block
#define NCHUNK (NN/CHUNK)     // 4 chunks per (batch, dir)
#define TILE 256              // target points per smem tile (== TPB)
#define BIGF 1e10f

// Scratch (no allocations allowed): hit flags + per-block partial sums.
__device__ unsigned char g_hit[2][BB*NN];          // [0]: hit_y, [1]: hit_x
__device__ float g_psum[2][BB][NCHUNK];            // sum of per-point min dists (valid only)
__device__ int   g_pcnt[2][BB][NCHUNK];            // valid source-point counts

__global__ void nl_init() {
    int i = blockIdx.x * blockDim.x + threadIdx.x;  // 8192 uint4s total
    ((uint4*)g_hit)[i] = make_uint4(0u, 0u, 0u, 0u);
}

// dir 0: source = x, target = y  (produces x_min sums, hit_y)
// dir 1: source = y, target = x  (produces y_min sums, hit_x)
__global__ void __launch_bounds__(TPB) nl_dir(const float* __restrict__ X,
                                              const float* __restrict__ Y) {
    const int dir = blockIdx.z;
    const int b   = blockIdx.y;
    const float* S = dir ? Y : X;
    const float* T = dir ? X : Y;
    const float* sb = S + (size_t)b * NN * 3;
    const float* tb = T + (size_t)b * NN * 3;

    __shared__ float4 sh[TILE];
    const int tid  = threadIdx.x;
    const int base = blockIdx.x * CHUNK;

    float sx[PPT], sy[PPT], sz[PPT], sn[PPT];
    bool  sval[PPT];
    float best[PPT];
    int   bidx[PPT];
#pragma unroll
    for (int p = 0; p < PPT; p++) {
        int i = base + tid + p * TPB;
        float a0 = sb[i*3+0], a1 = sb[i*3+1], a2 = sb[i*3+2];
        sx[p] = a0; sy[p] = a1; sz[p] = a2;
        sn[p] = a0*a0 + a1*a1 + a2*a2;
        sval[p] = ((a0 + a1 + a2) != 0.0f);   // reference zero-row mask
        best[p] = FLT_MAX;
        bidx[p] = 0;
    }

    for (int t0 = 0; t0 < NN; t0 += TILE) {
        {   // cooperative tile load: TILE == TPB, one point per thread
            int j = tid;
            float c0 = tb[(t0+j)*3+0];
            float c1 = tb[(t0+j)*3+1];
            float c2 = tb[(t0+j)*3+2];
            float tn = c0*c0 + c1*c1 + c2*c2;
            if ((c0 + c1 + c2) == 0.0f) tn += BIGF;  // fold invalid-target penalty into norm
            sh[j] = make_float4(c0, c1, c2, tn);
        }
        __syncthreads();
#pragma unroll 8
        for (int j = 0; j < TILE; j++) {
            float4 q = sh[j];
#pragma unroll
            for (int p = 0; p < PPT; p++) {
                float dot = fmaf(sx[p], q.x, fmaf(sy[p], q.y, sz[p] * q.z));
                float d   = fmaf(-2.0f, dot, sn[p] + q.w);   // ||s||^2 + ||t||^2 - 2 s.t (+BIG)
                if (d < best[p]) { best[p] = d; bidx[p] = t0 + j; }  // first-index tie-break
            }
        }
        __syncthreads();
    }

    // record hits (idempotent byte stores) + accumulate valid min sums
    float mysum = 0.0f; int mycnt = 0;
#pragma unroll
    for (int p = 0; p < PPT; p++) {
        if (sval[p]) {
            mysum += best[p];
            mycnt += 1;
            g_hit[dir][b * NN + bidx[p]] = (unsigned char)1;
        }
    }
#pragma unroll
    for (int o = 16; o > 0; o >>= 1) {
        mysum += __shfl_down_sync(0xffffffffu, mysum, o);
        mycnt += __shfl_down_sync(0xffffffffu, mycnt, o);
    }
    __shared__ float rs[TPB/32];
    __shared__ int   rc[TPB/32];
    if ((tid & 31) == 0) { rs[tid >> 5] = mysum; rc[tid >> 5] = mycnt; }
    __syncthreads();
    if (tid == 0) {
        float s = 0.0f; int c = 0;
#pragma unroll
        for (int w = 0; w < TPB/32; w++) { s += rs[w]; c += rc[w]; }
        g_psum[dir][b][blockIdx.x] = s;   // deterministic (fixed slot, fixed order)
        g_pcnt[dir][b][blockIdx.x] = c;
    }
}

// One block, warp-per-batch final reduction.
__global__ void __launch_bounds__(1024) nl_final(float* out, int out_size) {
    const int tid  = threadIdx.x;
    const int w    = tid >> 5;    // batch index (BB == 32 warps)
    const int lane = tid & 31;

    const unsigned int* hy = (const unsigned int*)(g_hit[0] + w * NN);
    const unsigned int* hx = (const unsigned int*)(g_hit[1] + w * NN);
    int covc = 0, qualc = 0;
#pragma unroll
    for (int k = 0; k < NN/4/32; k++) {          // 16 words per lane
        covc  += __popc(hy[lane + 32*k]);        // bytes are 0/1 -> popc == byte count
        qualc += __popc(hx[lane + 32*k]);
    }
    float sxs = (lane < NCHUNK) ? g_psum[0][w][lane] : 0.0f;
    float sys = (lane < NCHUNK) ? g_psum[1][w][lane] : 0.0f;
    int   cx  = (lane < NCHUNK) ? g_pcnt[0][w][lane] : 0;
    int   cy  = (lane < NCHUNK) ? g_pcnt[1][w][lane] : 0;
#pragma unroll
    for (int o = 16; o > 0; o >>= 1) {
        covc  += __shfl_xor_sync(0xffffffffu, covc,  o);
        qualc += __shfl_xor_sync(0xffffffffu, qualc, o);
        sxs   += __shfl_xor_sync(0xffffffffu, sxs,   o);
        sys   += __shfl_xor_sync(0xffffffffu, sys,   o);
        cx    += __shfl_xor_sync(0xffffffffu, cx,    o);
        cy    += __shfl_xor_sync(0xffffffffu, cy,    o);
    }

    __shared__ float scd[BB], scov[BB], squal[BB];
    if (lane == 0) {
        float nx = (float)cx, ny = (float)cy;
        scd[w]   = sxs / nx + sys / ny;
        scov[w]  = (float)covc  / ny;
        squal[w] = (float)qualc / nx;
    }
    __syncthreads();
    if (w == 0) {
        float cd = scd[lane], cov = scov[lane], qual = squal[lane];
#pragma unroll
        for (int o = 16; o > 0; o >>= 1) {
            cd   += __shfl_xor_sync(0xffffffffu, cd,   o);
            cov  += __shfl_xor_sync(0xffffffffu, cov,  o);
            qual += __shfl_xor_sync(0xffffffffu, qual, o);
        }
        if (lane == 0) {
            cd /= (float)BB; cov /= (float)BB; qual /= (float)BB;
            float val = cd - 1e-4f * cov - 1e-4f * qual;  // WCD=1, WCOV=WQUAL=1e-4
            if (out_size > 0) out[0] = val;
            if (out_size > 1) out[1] = cd;
            if (out_size > 2) out[2] = cov;
            if (out_size > 3) out[3] = qual;
        }
    }
}

extern "C" void kernel_launch(void* const* d_in, const int* in_sizes, int n_in,
                              void* d_out, int out_size) {
    const float* x = (const float*)d_in[0];
    const float* y = (const float*)d_in[1];
    float* out = (float*)d_out;

    nl_init<<<(2*BB*NN/16)/256, 256>>>();
    dim3 grid(NCHUNK, BB, 2);
    nl_dir<<<grid, TPB>>>(x, y);
    nl_final<<<1, 1024>>>(out, out_size);
}

// round 5
// speedup vs baseline: 1.0604x; 1.0604x over previous
#include <cuda_runtime.h>
#include <float.h>
#include <stdint.h>

#define BB 32
#define NN 2048
#define TPB 64
#define PPT 2                 // source points per thread
#define CHUNK (TPB*PPT)       // 128 source points per block
#define NCHUNK (NN/CHUNK)     // 16 chunks per (batch, dir) -> 1024 CTAs total
#define TILE 256              // target points per smem tile
#define BIGF 1e10f

// Scratch (no allocations allowed): hit flags + per-block partial sums.
__device__ unsigned char g_hit[2][BB*NN];          // [0]: hit_y, [1]: hit_x
__device__ float g_psum[2][BB][NCHUNK];            // sum of per-point min dists (valid only)
__device__ int   g_pcnt[2][BB][NCHUNK];            // valid source-point counts

__global__ void nl_init() {
    int i = blockIdx.x * blockDim.x + threadIdx.x;  // 8192 uint4s total
    ((uint4*)g_hit)[i] = make_uint4(0u, 0u, 0u, 0u);
}

// dir 0: source = x, target = y  (produces x_min sums, hit_y)
// dir 1: source = y, target = x  (produces y_min sums, hit_x)
__global__ void __launch_bounds__(TPB) nl_dir(const float* __restrict__ X,
                                              const float* __restrict__ Y) {
    const int dir = blockIdx.z;
    const int b   = blockIdx.y;
    const float* S = dir ? Y : X;
    const float* T = dir ? X : Y;
    const float* sb = S + (size_t)b * NN * 3;
    const float* tb = T + (size_t)b * NN * 3;

    __shared__ float4 sh[TILE];
    const int tid  = threadIdx.x;
    const int base = blockIdx.x * CHUNK;

    float sx[PPT], sy[PPT], sz[PPT], sn[PPT];
    bool  sval[PPT];
    float best[PPT];
    int   bidx[PPT];
#pragma unroll
    for (int p = 0; p < PPT; p++) {
        int i = base + tid + p * TPB;
        float a0 = sb[i*3+0], a1 = sb[i*3+1], a2 = sb[i*3+2];
        sx[p] = a0; sy[p] = a1; sz[p] = a2;
        sn[p] = a0*a0 + a1*a1 + a2*a2;
        sval[p] = ((a0 + a1 + a2) != 0.0f);   // reference zero-row mask
        best[p] = FLT_MAX;
        bidx[p] = 0;
    }

    for (int t0 = 0; t0 < NN; t0 += TILE) {
        // cooperative tile load: pre-scale coords by -2 and fold ||t||^2 (+BIG
        // for invalid targets) into the chain seed. Then per eval:
        //   c = fma(sx,qx', fma(sy,qy', fma(sz,qz', qw)))  = ||t||^2 - 2 s.t (+BIG)
        // and d_min = c_min + ||s||^2 recovered once per source at the end.
#pragma unroll
        for (int k = 0; k < TILE/TPB; k++) {
            int j = tid + k * TPB;
            float c0 = tb[(t0+j)*3+0];
            float c1 = tb[(t0+j)*3+1];
            float c2 = tb[(t0+j)*3+2];
            float tn = c0*c0 + c1*c1 + c2*c2;
            if ((c0 + c1 + c2) == 0.0f) tn += BIGF;
            sh[j] = make_float4(-2.0f*c0, -2.0f*c1, -2.0f*c2, tn);
        }
        __syncthreads();
#pragma unroll 8
        for (int j = 0; j < TILE; j++) {
            float4 q = sh[j];
#pragma unroll
            for (int p = 0; p < PPT; p++) {
                float c = fmaf(sx[p], q.x, fmaf(sy[p], q.y, fmaf(sz[p], q.z, q.w)));
                bool lt = (c < best[p]);                  // first-index tie-break (strict <)
                best[p] = lt ? c : best[p];               // -> FMNMX/FSEL
                bidx[p] = lt ? (t0 + j) : bidx[p];        // -> SEL
            }
        }
        __syncthreads();
    }

    // record hits (idempotent byte stores) + accumulate valid min sums
    float mysum = 0.0f; int mycnt = 0;
#pragma unroll
    for (int p = 0; p < PPT; p++) {
        if (sval[p]) {
            mysum += best[p] + sn[p];   // restore constant ||s||^2 offset
            mycnt += 1;
            g_hit[dir][b * NN + bidx[p]] = (unsigned char)1;
        }
    }
#pragma unroll
    for (int o = 16; o > 0; o >>= 1) {
        mysum += __shfl_down_sync(0xffffffffu, mysum, o);
        mycnt += __shfl_down_sync(0xffffffffu, mycnt, o);
    }
    __shared__ float rs[TPB/32];
    __shared__ int   rc[TPB/32];
    if ((tid & 31) == 0) { rs[tid >> 5] = mysum; rc[tid >> 5] = mycnt; }
    __syncthreads();
    if (tid == 0) {
        float s = 0.0f; int c = 0;
#pragma unroll
        for (int w = 0; w < TPB/32; w++) { s += rs[w]; c += rc[w]; }
        g_psum[dir][b][blockIdx.x] = s;   // deterministic (fixed slot, fixed order)
        g_pcnt[dir][b][blockIdx.x] = c;
    }
}

// One block, warp-per-batch final reduction.
__global__ void __launch_bounds__(1024) nl_final(float* out, int out_size) {
    const int tid  = threadIdx.x;
    const int w    = tid >> 5;    // batch index (BB == 32 warps)
    const int lane = tid & 31;

    const unsigned int* hy = (const unsigned int*)(g_hit[0] + w * NN);
    const unsigned int* hx = (const unsigned int*)(g_hit[1] + w * NN);
    int covc = 0, qualc = 0;
#pragma unroll
    for (int k = 0; k < NN/4/32; k++) {          // 16 words per lane
        covc  += __popc(hy[lane + 32*k]);        // bytes are 0/1 -> popc == byte count
        qualc += __popc(hx[lane + 32*k]);
    }
    float sxs = 0.0f, sys = 0.0f; int cx = 0, cy = 0;
    if (lane < NCHUNK) {
        sxs = g_psum[0][w][lane];
        sys = g_psum[1][w][lane];
        cx  = g_pcnt[0][w][lane];
        cy  = g_pcnt[1][w][lane];
    }
#pragma unroll
    for (int o = 16; o > 0; o >>= 1) {
        covc  += __shfl_xor_sync(0xffffffffu, covc,  o);
        qualc += __shfl_xor_sync(0xffffffffu, qualc, o);
        sxs   += __shfl_xor_sync(0xffffffffu, sxs,   o);
        sys   += __shfl_xor_sync(0xffffffffu, sys,   o);
        cx    += __shfl_xor_sync(0xffffffffu, cx,    o);
        cy    += __shfl_xor_sync(0xffffffffu, cy,    o);
    }

    __shared__ float scd[BB], scov[BB], squal[BB];
    if (lane == 0) {
        float nx = (float)cx, ny = (float)cy;
        scd[w]   = sxs / nx + sys / ny;
        scov[w]  = (float)covc  / ny;
        squal[w] = (float)qualc / nx;
    }
    __syncthreads();
    if (w == 0) {
        float cd = scd[lane], cov = scov[lane], qual = squal[lane];
#pragma unroll
        for (int o = 16; o > 0; o >>= 1) {
            cd   += __shfl_xor_sync(0xffffffffu, cd,   o);
            cov  += __shfl_xor_sync(0xffffffffu, cov,  o);
            qual += __shfl_xor_sync(0xffffffffu, qual, o);
        }
        if (lane == 0) {
            cd /= (float)BB; cov /= (float)BB; qual /= (float)BB;
            float val = cd - 1e-4f * cov - 1e-4f * qual;  // WCD=1, WCOV=WQUAL=1e-4
            if (out_size > 0) out[0] = val;
            if (out_size > 1) out[1] = cd;
            if (out_size > 2) out[2] = cov;
            if (out_size > 3) out[3] = qual;
        }
    }
}

extern "C" void kernel_launch(void* const* d_in, const int* in_sizes, int n_in,
                              void* d_out, int out_size) {
    const float* x = (const float*)d_in[0];
    const float* y = (const float*)d_in[1];
    float* out = (float*)d_out;

    nl_init<<<(2*BB*NN/16)/256, 256>>>();
    dim3 grid(NCHUNK, BB, 2);
    nl_dir<<<grid, TPB>>>(x, y);
    nl_final<<<1, 1024>>>(out, out_size);
}

// round 6
// speedup vs baseline: 1.3002x; 1.2261x over previous
#include <cuda_runtime.h>
#include <float.h>
#include <stdint.h>

#define BB 32
#define NN 2048
#define TPB 128
#define PPT 2
#define CHUNK (TPB*PPT)        // 256 sources per CTA
#define NCHUNK (NN/CHUNK)      // 8
#define NHALF 2
#define HALFN (NN/NHALF)       // 1024 targets per CTA
#define TILE 256
#define NPAIR (TILE/2)         // 128 pairs per tile (one per thread)
#define NTILE (HALFN/TILE)     // 4
#define BIGF 1e10f

// Static scratch (no allocations allowed).
__device__ float         g_val[2*NHALF*BB*NN];   // stuffed best key per (dir,half,b,src)
__device__ unsigned int  g_idx[2*NHALF*BB*NN];   // absolute argmin per (dir,half,b,src)
__device__ unsigned char g_hit[2][BB*NN];        // zeroed per-replay inside nl_merge
__device__ float4        g_red[2][BB];           // {sum_min, valid_cnt, hit_cnt, 0}

// ---- f32x2 packed helpers (sm_103a) ----
__device__ __forceinline__ unsigned long long pk2(float lo, float hi) {
    unsigned long long r;
    asm("mov.b64 %0, {%1, %2};" : "=l"(r) : "f"(lo), "f"(hi));
    return r;
}
__device__ __forceinline__ void upk2(unsigned long long v, float& lo, float& hi) {
    asm("mov.b64 {%0, %1}, %2;" : "=f"(lo), "=f"(hi) : "l"(v));
}
__device__ __forceinline__ unsigned long long fma2(unsigned long long a,
                                                   unsigned long long b,
                                                   unsigned long long c) {
    unsigned long long d;
    asm("fma.rn.f32x2 %0, %1, %2, %3;" : "=l"(d) : "l"(a), "l"(b), "l"(c));
    return d;
}

// Scan kernel: dir = z>>1, half = z&1. Each CTA: 256 sources vs 1024 targets.
// Inner loop tracks min over mantissa-stuffed keys:
//   key = (bits(c) & 0xFFFFFF00) | tile_local_target_index   (index 0..255)
// c = ||t||^2 - 2 s.t (+BIG for invalid targets); per-source const ||s||^2 omitted
// (doesn't change argmin). Exact distance recomputed in nl_merge.
__global__ void __launch_bounds__(TPB) nl_scan(const float* __restrict__ X,
                                               const float* __restrict__ Y) {
    const int z    = blockIdx.z;           // dir*2 + half
    const int dir  = z >> 1;
    const int half = z & 1;
    const int b    = blockIdx.y;
    const float* S = dir ? Y : X;
    const float* T = dir ? X : Y;
    const float* sb = S + (size_t)b * NN * 3;
    const float* tb = T + ((size_t)b * NN + half * HALFN) * 3;

    __shared__ ulonglong2 shA[NPAIR];   // (-2x packed, -2y packed)
    __shared__ ulonglong2 shB[NPAIR];   // (-2z packed, tn packed (+BIG))

    const int tid  = threadIdx.x;
    const int base = blockIdx.x * CHUNK;

    // Force the stuff-mask into a register so (bits & mask_reg) | imm is ONE LOP3.
    unsigned int mask;
    asm("mov.b32 %0, 0xFFFFFF00;" : "=r"(mask));

    unsigned long long sx2[PPT], sy2[PPT], sz2[PPT];
#pragma unroll
    for (int p = 0; p < PPT; p++) {
        int i = base + tid + p * TPB;
        float a0 = sb[i*3+0], a1 = sb[i*3+1], a2 = sb[i*3+2];
        sx2[p] = pk2(a0, a0);
        sy2[p] = pk2(a1, a1);
        sz2[p] = pk2(a2, a2);
    }

    float gval[PPT];
    int   gtile[PPT];
#pragma unroll
    for (int p = 0; p < PPT; p++) { gval[p] = FLT_MAX; gtile[p] = 0; }

#pragma unroll
    for (int t = 0; t < NTILE; t++) {
        {   // tile load: one pair per thread
            int j = t * TILE + 2 * tid;
            float u0 = tb[j*3+0], u1 = tb[j*3+1], u2 = tb[j*3+2];
            float v0 = tb[j*3+3], v1 = tb[j*3+4], v2 = tb[j*3+5];
            float un = u0*u0 + u1*u1 + u2*u2;
            float vn = v0*v0 + v1*v1 + v2*v2;
            if ((u0 + u1 + u2) == 0.0f) un += BIGF;
            if ((v0 + v1 + v2) == 0.0f) vn += BIGF;
            shA[tid] = make_ulonglong2(pk2(-2.0f*u0, -2.0f*v0), pk2(-2.0f*u1, -2.0f*v1));
            shB[tid] = make_ulonglong2(pk2(-2.0f*u2, -2.0f*v2), pk2(un, vn));
        }
        __syncthreads();

        float beste[PPT], besto[PPT];
#pragma unroll
        for (int p = 0; p < PPT; p++) { beste[p] = FLT_MAX; besto[p] = FLT_MAX; }

#pragma unroll
        for (int k = 0; k < NPAIR; k++) {      // fully unrolled: 2*k is an immediate
            ulonglong2 a  = shA[k];
            ulonglong2 bq = shB[k];
#pragma unroll
            for (int p = 0; p < PPT; p++) {
                unsigned long long c2 =
                    fma2(sx2[p], a.x, fma2(sy2[p], a.y, fma2(sz2[p], bq.x, bq.y)));
                float clo, chi;
                upk2(c2, clo, chi);
                unsigned int kl = (__float_as_uint(clo) & mask) | (unsigned)(2*k);
                unsigned int kh = (__float_as_uint(chi) & mask) | (unsigned)(2*k + 1);
                beste[p] = fminf(beste[p], __uint_as_float(kl));   // independent chains
                besto[p] = fminf(besto[p], __uint_as_float(kh));
            }
        }
        __syncthreads();

#pragma unroll
        for (int p = 0; p < PPT; p++) {        // per-tile tournament
            float tbst = fminf(beste[p], besto[p]);
            bool lt = (tbst < gval[p]);        // strict <: earlier tile wins ties
            gval[p]  = lt ? tbst : gval[p];
            gtile[p] = lt ? t : gtile[p];
        }
    }

#pragma unroll
    for (int p = 0; p < PPT; p++) {
        unsigned int rel = __float_as_uint(gval[p]) & 0xFFu;
        unsigned int idx = half * HALFN + gtile[p] * TILE + rel;  // absolute target index
        int s = base + tid + p * TPB;
        size_t o = ((size_t)z * BB + b) * NN + s;
        g_val[o] = gval[p];
        g_idx[o] = idx;
    }
}

// Merge: one block per (dir, b). Combines halves, recomputes exact distance of
// the winner, applies validity mask, records + counts hits, reduces sums.
__global__ void __launch_bounds__(256) nl_merge(const float* __restrict__ X,
                                                const float* __restrict__ Y) {
    const int blk = blockIdx.x;       // 0..63
    const int dir = blk >> 5;
    const int b   = blk & 31;
    const float* S = dir ? Y : X;
    const float* T = dir ? X : Y;
    const float* sb = S + (size_t)b * NN * 3;
    const float* tv = T + (size_t)b * NN * 3;
    unsigned char* hit = &g_hit[dir][b * NN];
    const int tid = threadIdx.x;

    if (tid < NN/16) ((uint4*)hit)[tid] = make_uint4(0u,0u,0u,0u);  // zero 2048 bytes
    __syncthreads();

    float sum = 0.0f; int cnt = 0;
    for (int s = tid; s < NN; s += 256) {
        size_t o0 = ((size_t)(dir*2+0) * BB + b) * NN + s;
        size_t o1 = ((size_t)(dir*2+1) * BB + b) * NN + s;
        float v0 = g_val[o0], v1 = g_val[o1];
        unsigned int idx = (v0 <= v1) ? g_idx[o0] : g_idx[o1];  // tie -> half 0 (lower idx)
        float a0 = sb[s*3+0], a1 = sb[s*3+1], a2 = sb[s*3+2];
        if ((a0 + a1 + a2) != 0.0f) {                            // valid source
            float t0 = tv[idx*3+0], t1 = tv[idx*3+1], t2 = tv[idx*3+2];
            float tn = t0*t0 + t1*t1 + t2*t2;
            if ((t0 + t1 + t2) == 0.0f) tn += BIGF;
            float sn  = a0*a0 + a1*a1 + a2*a2;
            float dot = fmaf(a0, t0, fmaf(a1, t1, a2 * t2));
            sum += fmaf(-2.0f, dot, sn + tn);                    // exact min distance
            cnt += 1;
            hit[idx] = (unsigned char)1;                          // idempotent
        }
    }
    __syncthreads();

    int hc = 0;
    const unsigned int* hw = (const unsigned int*)hit;
    for (int k = tid; k < NN/4; k += 256) hc += __popc(hw[k] & 0x01010101u);

#pragma unroll
    for (int o = 16; o > 0; o >>= 1) {
        sum += __shfl_down_sync(0xffffffffu, sum, o);
        cnt += __shfl_down_sync(0xffffffffu, cnt, o);
        hc  += __shfl_down_sync(0xffffffffu, hc,  o);
    }
    __shared__ float rs[8]; __shared__ int rc[8], rh[8];
    if ((tid & 31) == 0) { rs[tid>>5] = sum; rc[tid>>5] = cnt; rh[tid>>5] = hc; }
    __syncthreads();
    if (tid == 0) {
        float s2 = 0.0f; int c2 = 0, h2 = 0;
#pragma unroll
        for (int w = 0; w < 8; w++) { s2 += rs[w]; c2 += rc[w]; h2 += rh[w]; }
        g_red[dir][b] = make_float4(s2, (float)c2, (float)h2, 0.0f);
    }
}

__global__ void nl_final(float* out, int out_size) {
    const int lane = threadIdx.x;    // 32 threads, one batch each
    float4 r0 = g_red[0][lane];      // dir0: x->y (sum xmin, nx, hit_y)
    float4 r1 = g_red[1][lane];      // dir1: y->x (sum ymin, ny, hit_x)
    float cd   = r0.x / r0.y + r1.x / r1.y;
    float cov  = r0.z / r1.y;        // hit_y / ny
    float qual = r1.z / r0.y;        // hit_x / nx
#pragma unroll
    for (int o = 16; o > 0; o >>= 1) {
        cd   += __shfl_xor_sync(0xffffffffu, cd,   o);
        cov  += __shfl_xor_sync(0xffffffffu, cov,  o);
        qual += __shfl_xor_sync(0xffffffffu, qual, o);
    }
    if (lane == 0) {
        cd /= (float)BB; cov /= (float)BB; qual /= (float)BB;
        float val = cd - 1e-4f * cov - 1e-4f * qual;
        if (out_size > 0) out[0] = val;
        if (out_size > 1) out[1] = cd;
        if (out_size > 2) out[2] = cov;
        if (out_size > 3) out[3] = qual;
    }
}

extern "C" void kernel_launch(void* const* d_in, const int* in_sizes, int n_in,
                              void* d_out, int out_size) {
    const float* x = (const float*)d_in[0];
    const float* y = (const float*)d_in[1];
    float* out = (float*)d_out;

    dim3 grid(NCHUNK, BB, 2 * NHALF);   // (8, 32, 4) = 1024 CTAs
    nl_scan<<<grid, TPB>>>(x, y);
    nl_merge<<<64, 256>>>(x, y);
    nl_final<<<1, 32>>>(out, out_size);
}

// round 7
// speedup vs baseline: 1.8064x; 1.3894x over previous
#include <cuda_runtime.h>
#include <float.h>
#include <stdint.h>

#define BB 32
#define NN 2048
#define TPB 128
#define PPT 2
#define CHUNK (TPB*PPT)        // 256 sources per CTA
#define NCHUNK (NN/CHUNK)      // 8
#define NHALF 4
#define HALFN (NN/NHALF)       // 512 targets per CTA
#define TILE 256
#define NPAIR (TILE/2)         // 128 pairs per tile (one per thread)
#define NQUAD (TILE/4)         // 64 quads per tile
#define NTILE (HALFN/TILE)     // 2
#define BIGF 1e10f

// Static scratch (no allocations allowed).
__device__ float         g_val[2*NHALF*BB*NN];   // stuffed best key per (dir,half,b,src)
__device__ unsigned int  g_idx[2*NHALF*BB*NN];   // winning-quad base index (absolute)
__device__ unsigned char g_hit[2][BB*NN];        // zeroed per-replay inside nl_merge
__device__ float4        g_red[2][BB];           // {sum_min, valid_cnt, hit_cnt, 0}

// ---- f32x2 packed helpers (sm_103a) ----
__device__ __forceinline__ unsigned long long pk2(float lo, float hi) {
    unsigned long long r;
    asm("mov.b64 %0, {%1, %2};" : "=l"(r) : "f"(lo), "f"(hi));
    return r;
}
__device__ __forceinline__ void upk2(unsigned long long v, float& lo, float& hi) {
    asm("mov.b64 {%0, %1}, %2;" : "=f"(lo), "=f"(hi) : "l"(v));
}
__device__ __forceinline__ unsigned long long fma2(unsigned long long a,
                                                   unsigned long long b,
                                                   unsigned long long c) {
    unsigned long long d;
    asm("fma.rn.f32x2 %0, %1, %2, %3;" : "=l"(d) : "l"(a), "l"(b), "l"(c));
    return d;
}

// Scan: z = dir*NHALF + half. Each CTA: 256 sources vs 512 targets.
// Quad tournament: raw min over 4 targets (3 FMNMX), stuff 6-bit quad index
// into mantissa low bits of the winner (1 LOP3), accumulate (1 FMNMX).
// c = ||t||^2 - 2 s.t (+BIG invalid target); per-source ||s||^2 const omitted
// (argmin invariant). Winning quad's 4 exact distances recomputed in nl_merge.
__global__ void __launch_bounds__(TPB) nl_scan(const float* __restrict__ X,
                                               const float* __restrict__ Y) {
    const int z    = blockIdx.z;           // dir*NHALF + half
    const int dir  = z >> 2;
    const int half = z & 3;
    const int b    = blockIdx.y;
    const float* S = dir ? Y : X;
    const float* T = dir ? X : Y;
    const float* sb = S + (size_t)b * NN * 3;
    const float* tb = T + ((size_t)b * NN + half * HALFN) * 3;

    __shared__ ulonglong2 shA[NPAIR];   // (-2x packed, -2y packed)
    __shared__ ulonglong2 shB[NPAIR];   // (-2z packed, tn packed (+BIG))

    const int tid  = threadIdx.x;
    const int base = blockIdx.x * CHUNK;

    // keep the stuff-mask in a register: (bits & mask) | q is one LOP3
    unsigned int mask;
    asm("mov.b32 %0, 0xFFFFFFC0;" : "=r"(mask));

    unsigned long long sx2[PPT], sy2[PPT], sz2[PPT];
#pragma unroll
    for (int p = 0; p < PPT; p++) {
        int i = base + tid + p * TPB;
        float a0 = sb[i*3+0], a1 = sb[i*3+1], a2 = sb[i*3+2];
        sx2[p] = pk2(a0, a0);
        sy2[p] = pk2(a1, a1);
        sz2[p] = pk2(a2, a2);
    }

    float gkey[PPT];
    int   gtile[PPT];
#pragma unroll
    for (int p = 0; p < PPT; p++) { gkey[p] = FLT_MAX; gtile[p] = 0; }

#pragma unroll
    for (int t = 0; t < NTILE; t++) {
        {   // tile load: one target-pair per thread
            int j = t * TILE + 2 * tid;
            float u0 = tb[j*3+0], u1 = tb[j*3+1], u2 = tb[j*3+2];
            float v0 = tb[j*3+3], v1 = tb[j*3+4], v2 = tb[j*3+5];
            float un = u0*u0 + u1*u1 + u2*u2;
            float vn = v0*v0 + v1*v1 + v2*v2;
            if ((u0 + u1 + u2) == 0.0f) un += BIGF;
            if ((v0 + v1 + v2) == 0.0f) vn += BIGF;
            shA[tid] = make_ulonglong2(pk2(-2.0f*u0, -2.0f*v0), pk2(-2.0f*u1, -2.0f*v1));
            shB[tid] = make_ulonglong2(pk2(-2.0f*u2, -2.0f*v2), pk2(un, vn));
        }
        __syncthreads();

        float best[PPT];
#pragma unroll
        for (int p = 0; p < PPT; p++) best[p] = FLT_MAX;

#pragma unroll 16
        for (int q = 0; q < NQUAD; q++) {
            ulonglong2 a0 = shA[2*q],   b0 = shB[2*q];
            ulonglong2 a1 = shA[2*q+1], b1 = shB[2*q+1];
#pragma unroll
            for (int p = 0; p < PPT; p++) {
                unsigned long long ca =
                    fma2(sx2[p], a0.x, fma2(sy2[p], a0.y, fma2(sz2[p], b0.x, b0.y)));
                unsigned long long cb =
                    fma2(sx2[p], a1.x, fma2(sy2[p], a1.y, fma2(sz2[p], b1.x, b1.y)));
                float l0, h0, l1, h1;
                upk2(ca, l0, h0);
                upk2(cb, l1, h1);
                float m = fminf(fminf(l0, h0), fminf(l1, h1));     // 3 FMNMX (raw)
                unsigned int key = (__float_as_uint(m) & mask) | (unsigned)q;  // 1 LOP3
                best[p] = fminf(best[p], __uint_as_float(key));    // 1 FMNMX
            }
        }
        __syncthreads();

#pragma unroll
        for (int p = 0; p < PPT; p++) {      // cross-tile tournament (strict <)
            bool lt = (best[p] < gkey[p]);
            gkey[p]  = lt ? best[p] : gkey[p];
            gtile[p] = lt ? t : gtile[p];
        }
    }

#pragma unroll
    for (int p = 0; p < PPT; p++) {
        unsigned int quad = __float_as_uint(gkey[p]) & 0x3Fu;
        unsigned int idx  = half * HALFN + gtile[p] * TILE + quad * 4;  // quad base
        int s = base + tid + p * TPB;
        size_t o = ((size_t)z * BB + b) * NN + s;
        g_val[o] = gkey[p];
        g_idx[o] = idx;
    }
}

// Merge: one block per (dir, b). Picks winning half per source, recomputes the
// winning quad's 4 exact distances, applies validity, records hits, reduces.
__global__ void __launch_bounds__(512) nl_merge(const float* __restrict__ X,
                                                const float* __restrict__ Y) {
    const int blk = blockIdx.x;       // 0..63
    const int dir = blk >> 5;
    const int b   = blk & 31;
    const float* S = dir ? Y : X;
    const float* T = dir ? X : Y;
    const float* sb = S + (size_t)b * NN * 3;
    const float* tv = T + (size_t)b * NN * 3;
    unsigned char* hit = &g_hit[dir][b * NN];
    const int tid = threadIdx.x;

    if (tid < NN/16) ((uint4*)hit)[tid] = make_uint4(0u,0u,0u,0u);  // zero 2048 bytes
    __syncthreads();

    float sum = 0.0f; int cnt = 0;
    for (int s = tid; s < NN; s += 512) {
        // pick winning half (ascending, strict < -> lowest half/index on ties)
        float bkey = FLT_MAX; unsigned int qbase = 0;
#pragma unroll
        for (int h = 0; h < NHALF; h++) {
            size_t o = ((size_t)(dir*NHALF + h) * BB + b) * NN + s;
            float k = g_val[o];
            if (k < bkey) { bkey = k; qbase = g_idx[o]; }
        }
        float a0 = sb[s*3+0], a1 = sb[s*3+1], a2 = sb[s*3+2];
        if ((a0 + a1 + a2) != 0.0f) {                       // valid source
            float sn = a0*a0 + a1*a1 + a2*a2;
            float bd = FLT_MAX; unsigned int bi = qbase;
#pragma unroll
            for (int i = 0; i < 4; i++) {                   // exact recompute of quad
                unsigned int idx = qbase + i;
                float t0 = tv[idx*3+0], t1 = tv[idx*3+1], t2 = tv[idx*3+2];
                float tn = t0*t0 + t1*t1 + t2*t2;
                if ((t0 + t1 + t2) == 0.0f) tn += BIGF;
                float dot = fmaf(a0, t0, fmaf(a1, t1, a2 * t2));
                float d   = fmaf(-2.0f, dot, sn + tn);
                if (d < bd) { bd = d; bi = idx; }           // first-index tie-break
            }
            sum += bd;
            cnt += 1;
            hit[bi] = (unsigned char)1;                      // idempotent
        }
    }
    __syncthreads();

    int hc = 0;
    const unsigned int* hw = (const unsigned int*)hit;
    for (int k = tid; k < NN/4; k += 512) hc += __popc(hw[k] & 0x01010101u);

#pragma unroll
    for (int o = 16; o > 0; o >>= 1) {
        sum += __shfl_down_sync(0xffffffffu, sum, o);
        cnt += __shfl_down_sync(0xffffffffu, cnt, o);
        hc  += __shfl_down_sync(0xffffffffu, hc,  o);
    }
    __shared__ float rs[16]; __shared__ int rc[16], rh[16];
    if ((tid & 31) == 0) { rs[tid>>5] = sum; rc[tid>>5] = cnt; rh[tid>>5] = hc; }
    __syncthreads();
    if (tid == 0) {
        float s2 = 0.0f; int c2 = 0, h2 = 0;
#pragma unroll
        for (int w = 0; w < 16; w++) { s2 += rs[w]; c2 += rc[w]; h2 += rh[w]; }
        g_red[dir][b] = make_float4(s2, (float)c2, (float)h2, 0.0f);
    }
}

__global__ void nl_final(float* out, int out_size) {
    const int lane = threadIdx.x;    // 32 threads, one batch each
    float4 r0 = g_red[0][lane];      // dir0: x->y (sum xmin, nx, hit_y)
    float4 r1 = g_red[1][lane];      // dir1: y->x (sum ymin, ny, hit_x)
    float cd   = r0.x / r0.y + r1.x / r1.y;
    float cov  = r0.z / r1.y;        // hit_y / ny
    float qual = r1.z / r0.y;        // hit_x / nx
#pragma unroll
    for (int o = 16; o > 0; o >>= 1) {
        cd   += __shfl_xor_sync(0xffffffffu, cd,   o);
        cov  += __shfl_xor_sync(0xffffffffu, cov,  o);
        qual += __shfl_xor_sync(0xffffffffu, qual, o);
    }
    if (lane == 0) {
        cd /= (float)BB; cov /= (float)BB; qual /= (float)BB;
        float val = cd - 1e-4f * cov - 1e-4f * qual;
        if (out_size > 0) out[0] = val;
        if (out_size > 1) out[1] = cd;
        if (out_size > 2) out[2] = cov;
        if (out_size > 3) out[3] = qual;
    }
}

extern "C" void kernel_launch(void* const* d_in, const int* in_sizes, int n_in,
                              void* d_out, int out_size) {
    const float* x = (const float*)d_in[0];
    const float* y = (const float*)d_in[1];
    float* out = (float*)d_out;

    dim3 grid(NCHUNK, BB, 2 * NHALF);   // (8, 32, 8) = 2048 CTAs
    nl_scan<<<grid, TPB>>>(x, y);
    nl_merge<<<64, 512>>>(x, y);
    nl_final<<<1, 32>>>(out, out_size);
}

// round 8
// speedup vs baseline: 1.8933x; 1.0481x over previous
#include <cuda_runtime.h>
#include <float.h>
#include <stdint.h>

#define BB 32
#define NN 2048
#define TPB 128
#define PPT 4
#define CHUNK (TPB*PPT)        // 512 sources per CTA
#define NCHUNK (NN/CHUNK)      // 4
#define NHALF 4
#define HALFN (NN/NHALF)       // 512 targets per CTA
#define TILE 256
#define NPAIR (TILE/2)         // 128 pairs per tile (one per thread)
#define NQUAD (TILE/4)         // 64 quads per tile
#define NTILE (HALFN/TILE)     // 2
#define BIGF 1e10f

// Static scratch (no allocations allowed).
__device__ float         g_val[2*NHALF*BB*NN];   // stuffed best key per (dir,half,b,src)
__device__ unsigned int  g_idx[2*NHALF*BB*NN];   // winning-quad base index (absolute)
__device__ unsigned char g_hit[2][BB*NN];        // zeroed per-replay inside nl_merge
__device__ float4        g_red[2][BB];           // {sum_min, valid_cnt, hit_cnt, 0}

// ---- f32x2 packed helpers (sm_103a) ----
__device__ __forceinline__ unsigned long long pk2(float lo, float hi) {
    unsigned long long r;
    asm("mov.b64 %0, {%1, %2};" : "=l"(r) : "f"(lo), "f"(hi));
    return r;
}
__device__ __forceinline__ void upk2(unsigned long long v, float& lo, float& hi) {
    asm("mov.b64 {%0, %1}, %2;" : "=f"(lo), "=f"(hi) : "l"(v));
}
__device__ __forceinline__ unsigned long long fma2(unsigned long long a,
                                                   unsigned long long b,
                                                   unsigned long long c) {
    unsigned long long d;
    asm("fma.rn.f32x2 %0, %1, %2, %3;" : "=l"(d) : "l"(a), "l"(b), "l"(c));
    return d;
}

// Scan: z = dir*NHALF + half. Each CTA: 512 sources vs 512 targets.
// Quad tournament: raw min over 4 targets (3 FMNMX), stuff 6-bit quad index
// into mantissa low bits of the winner (1 LOP3), accumulate (1 FMNMX).
// c = ||t||^2 - 2 s.t (+BIG invalid target); per-source ||s||^2 const omitted
// (argmin invariant). Winning quad's 4 exact distances recomputed in nl_merge.
__global__ void __launch_bounds__(TPB) nl_scan(const float* __restrict__ X,
                                               const float* __restrict__ Y) {
    const int z    = blockIdx.z;           // dir*NHALF + half
    const int dir  = z >> 2;
    const int half = z & 3;
    const int b    = blockIdx.y;
    const float* S = dir ? Y : X;
    const float* T = dir ? X : Y;
    const float* sb = S + (size_t)b * NN * 3;
    const float* tb = T + ((size_t)b * NN + half * HALFN) * 3;

    __shared__ ulonglong2 shA[NPAIR];   // (-2x packed, -2y packed)
    __shared__ ulonglong2 shB[NPAIR];   // (-2z packed, tn packed (+BIG))

    const int tid  = threadIdx.x;
    const int base = blockIdx.x * CHUNK;

    // keep the stuff-mask in a register: (bits & mask) | q is one LOP3
    unsigned int mask;
    asm("mov.b32 %0, 0xFFFFFFC0;" : "=r"(mask));

    unsigned long long sx2[PPT], sy2[PPT], sz2[PPT];
#pragma unroll
    for (int p = 0; p < PPT; p++) {
        int i = base + tid + p * TPB;
        float a0 = sb[i*3+0], a1 = sb[i*3+1], a2 = sb[i*3+2];
        sx2[p] = pk2(a0, a0);
        sy2[p] = pk2(a1, a1);
        sz2[p] = pk2(a2, a2);
    }

    float gkey[PPT];
    int   gtile[PPT];
#pragma unroll
    for (int p = 0; p < PPT; p++) { gkey[p] = FLT_MAX; gtile[p] = 0; }

#pragma unroll
    for (int t = 0; t < NTILE; t++) {
        {   // tile load: one target-pair per thread
            int j = t * TILE + 2 * tid;
            float u0 = tb[j*3+0], u1 = tb[j*3+1], u2 = tb[j*3+2];
            float v0 = tb[j*3+3], v1 = tb[j*3+4], v2 = tb[j*3+5];
            float un = u0*u0 + u1*u1 + u2*u2;
            float vn = v0*v0 + v1*v1 + v2*v2;
            if ((u0 + u1 + u2) == 0.0f) un += BIGF;
            if ((v0 + v1 + v2) == 0.0f) vn += BIGF;
            shA[tid] = make_ulonglong2(pk2(-2.0f*u0, -2.0f*v0), pk2(-2.0f*u1, -2.0f*v1));
            shB[tid] = make_ulonglong2(pk2(-2.0f*u2, -2.0f*v2), pk2(un, vn));
        }
        __syncthreads();

        float best[PPT];
#pragma unroll
        for (int p = 0; p < PPT; p++) best[p] = FLT_MAX;

#pragma unroll 8
        for (int q = 0; q < NQUAD; q++) {
            ulonglong2 a0 = shA[2*q],   b0 = shB[2*q];
            ulonglong2 a1 = shA[2*q+1], b1 = shB[2*q+1];
#pragma unroll
            for (int p = 0; p < PPT; p++) {
                unsigned long long ca =
                    fma2(sx2[p], a0.x, fma2(sy2[p], a0.y, fma2(sz2[p], b0.x, b0.y)));
                unsigned long long cb =
                    fma2(sx2[p], a1.x, fma2(sy2[p], a1.y, fma2(sz2[p], b1.x, b1.y)));
                float l0, h0, l1, h1;
                upk2(ca, l0, h0);
                upk2(cb, l1, h1);
                float m = fminf(fminf(l0, h0), fminf(l1, h1));     // 3 FMNMX (raw)
                unsigned int key = (__float_as_uint(m) & mask) | (unsigned)q;  // 1 LOP3
                best[p] = fminf(best[p], __uint_as_float(key));    // 1 FMNMX
            }
        }
        __syncthreads();

#pragma unroll
        for (int p = 0; p < PPT; p++) {      // cross-tile tournament (strict <)
            bool lt = (best[p] < gkey[p]);
            gkey[p]  = lt ? best[p] : gkey[p];
            gtile[p] = lt ? t : gtile[p];
        }
    }

#pragma unroll
    for (int p = 0; p < PPT; p++) {
        unsigned int quad = __float_as_uint(gkey[p]) & 0x3Fu;
        unsigned int idx  = half * HALFN + gtile[p] * TILE + quad * 4;  // quad base
        int s = base + tid + p * TPB;
        size_t o = ((size_t)z * BB + b) * NN + s;
        g_val[o] = gkey[p];
        g_idx[o] = idx;
    }
}

// Merge: one block per (dir, b). Picks winning half per source, recomputes the
// winning quad's 4 exact distances, applies validity, records hits, reduces.
__global__ void __launch_bounds__(512) nl_merge(const float* __restrict__ X,
                                                const float* __restrict__ Y) {
    const int blk = blockIdx.x;       // 0..63
    const int dir = blk >> 5;
    const int b   = blk & 31;
    const float* S = dir ? Y : X;
    const float* T = dir ? X : Y;
    const float* sb = S + (size_t)b * NN * 3;
    const float* tv = T + (size_t)b * NN * 3;
    unsigned char* hit = &g_hit[dir][b * NN];
    const int tid = threadIdx.x;

    if (tid < NN/16) ((uint4*)hit)[tid] = make_uint4(0u,0u,0u,0u);  // zero 2048 bytes
    __syncthreads();

    float sum = 0.0f; int cnt = 0;
    for (int s = tid; s < NN; s += 512) {
        // pick winning half (ascending, strict < -> lowest half/index on ties)
        float bkey = FLT_MAX; unsigned int qbase = 0;
#pragma unroll
        for (int h = 0; h < NHALF; h++) {
            size_t o = ((size_t)(dir*NHALF + h) * BB + b) * NN + s;
            float k = g_val[o];
            if (k < bkey) { bkey = k; qbase = g_idx[o]; }
        }
        float a0 = sb[s*3+0], a1 = sb[s*3+1], a2 = sb[s*3+2];
        if ((a0 + a1 + a2) != 0.0f) {                       // valid source
            float sn = a0*a0 + a1*a1 + a2*a2;
            float bd = FLT_MAX; unsigned int bi = qbase;
#pragma unroll
            for (int i = 0; i < 4; i++) {                   // exact recompute of quad
                unsigned int idx = qbase + i;
                float t0 = tv[idx*3+0], t1 = tv[idx*3+1], t2 = tv[idx*3+2];
                float tn = t0*t0 + t1*t1 + t2*t2;
                if ((t0 + t1 + t2) == 0.0f) tn += BIGF;
                float dot = fmaf(a0, t0, fmaf(a1, t1, a2 * t2));
                float d   = fmaf(-2.0f, dot, sn + tn);
                if (d < bd) { bd = d; bi = idx; }           // first-index tie-break
            }
            sum += bd;
            cnt += 1;
            hit[bi] = (unsigned char)1;                      // idempotent
        }
    }
    __syncthreads();

    int hc = 0;
    const unsigned int* hw = (const unsigned int*)hit;
    for (int k = tid; k < NN/4; k += 512) hc += __popc(hw[k] & 0x01010101u);

#pragma unroll
    for (int o = 16; o > 0; o >>= 1) {
        sum += __shfl_down_sync(0xffffffffu, sum, o);
        cnt += __shfl_down_sync(0xffffffffu, cnt, o);
        hc  += __shfl_down_sync(0xffffffffu, hc,  o);
    }
    __shared__ float rs[16]; __shared__ int rc[16], rh[16];
    if ((tid & 31) == 0) { rs[tid>>5] = sum; rc[tid>>5] = cnt; rh[tid>>5] = hc; }
    __syncthreads();
    if (tid == 0) {
        float s2 = 0.0f; int c2 = 0, h2 = 0;
#pragma unroll
        for (int w = 0; w < 16; w++) { s2 += rs[w]; c2 += rc[w]; h2 += rh[w]; }
        g_red[dir][b] = make_float4(s2, (float)c2, (float)h2, 0.0f);
    }
}

__global__ void nl_final(float* out, int out_size) {
    const int lane = threadIdx.x;    // 32 threads, one batch each
    float4 r0 = g_red[0][lane];      // dir0: x->y (sum xmin, nx, hit_y)
    float4 r1 = g_red[1][lane];      // dir1: y->x (sum ymin, ny, hit_x)
    float cd   = r0.x / r0.y + r1.x / r1.y;
    float cov  = r0.z / r1.y;        // hit_y / ny
    float qual = r1.z / r0.y;        // hit_x / nx
#pragma unroll
    for (int o = 16; o > 0; o >>= 1) {
        cd   += __shfl_xor_sync(0xffffffffu, cd,   o);
        cov  += __shfl_xor_sync(0xffffffffu, cov,  o);
        qual += __shfl_xor_sync(0xffffffffu, qual, o);
    }
    if (lane == 0) {
        cd /= (float)BB; cov /= (float)BB; qual /= (float)BB;
        float val = cd - 1e-4f * cov - 1e-4f * qual;
        if (out_size > 0) out[0] = val;
        if (out_size > 1) out[1] = cd;
        if (out_size > 2) out[2] = cov;
        if (out_size > 3) out[3] = qual;
    }
}

extern "C" void kernel_launch(void* const* d_in, const int* in_sizes, int n_in,
                              void* d_out, int out_size) {
    const float* x = (const float*)d_in[0];
    const float* y = (const float*)d_in[1];
    float* out = (float*)d_out;

    dim3 grid(NCHUNK, BB, 2 * NHALF);   // (4, 32, 8) = 1024 CTAs
    nl_scan<<<grid, TPB>>>(x, y);
    nl_merge<<<64, 512>>>(x, y);
    nl_final<<<1, 32>>>(out, out_size);
}